// round 2
// baseline (speedup 1.0000x reference)
#include <cuda_runtime.h>

#define DIM 256
#define NCOL 16
#define BATCH 65536

// Scratch (no allocations allowed)
__device__ float2 g_M[NCOL][DIM];   // 16 relevant columns of the variational unitary
__device__ float  g_C[81 * 8];      // separable quadratic-form tensor, [m][i]

__device__ __forceinline__ float2 cmul(float2 a, float2 b) {
    return make_float2(a.x * b.x - a.y * b.y, a.x * b.y + a.y * b.x);
}

// ---------------------------------------------------------------------------
// K1: simulate the variational circuit on the 16 relevant basis columns.
// One block per column. Per layer: 8 FUSED (RZ*RY*RX) 1q gates + the CNOT
// chain collapsed to the closed-form permutation new[j] = old[j ^ (j>>1)].
// ---------------------------------------------------------------------------
__global__ void setup_sim(const float* __restrict__ params) {
    __shared__ float2 st[DIM];
    __shared__ float2 G[16][4];
    int t = threadIdx.x;            // 0..127
    int col = blockIdx.x;           // 0..15

    if (t < 16) {
        int layer = t >> 3, w = t & 7;
        const float* p = params + layer * 24 + w * 3;
        float cx, sx, cy, sy, cz, sz;
        sincosf(0.5f * p[0], &sx, &cx);
        sincosf(0.5f * p[1], &sy, &cy);
        sincosf(0.5f * p[2], &sz, &cz);
        // RY*RX
        float2 a00 = make_float2( cy * cx,  sy * sx);
        float2 a01 = make_float2(-sy * cx, -cy * sx);
        float2 a10 = make_float2( sy * cx, -cy * sx);
        float2 a11 = make_float2( cy * cx, -sy * sx);
        // RZ * (RY*RX)
        float2 e0 = make_float2(cz, -sz), e1 = make_float2(cz, sz);
        G[t][0] = cmul(e0, a00);
        G[t][1] = cmul(e0, a01);
        G[t][2] = cmul(e1, a10);
        G[t][3] = cmul(e1, a11);
    }
    st[t] = make_float2(0.f, 0.f);
    st[t + 128] = make_float2(0.f, 0.f);
    __syncthreads();
    if (t == 0) st[col << 4] = make_float2(1.f, 0.f);

    for (int layer = 0; layer < 2; ++layer) {
        for (int w = 0; w < 8; ++w) {
            __syncthreads();
            int bit = 1 << (7 - w);
            float2 g00 = G[layer * 8 + w][0], g01 = G[layer * 8 + w][1];
            float2 g10 = G[layer * 8 + w][2], g11 = G[layer * 8 + w][3];
            int j0 = ((t & ~(bit - 1)) << 1) | (t & (bit - 1));
            int j1 = j0 | bit;
            float2 a0 = st[j0], a1 = st[j1];
            float2 n0, n1;
            n0.x = g00.x * a0.x - g00.y * a0.y + g01.x * a1.x - g01.y * a1.y;
            n0.y = g00.x * a0.y + g00.y * a0.x + g01.x * a1.y + g01.y * a1.x;
            n1.x = g10.x * a0.x - g10.y * a0.y + g11.x * a1.x - g11.y * a1.y;
            n1.y = g10.x * a0.y + g10.y * a0.x + g11.x * a1.y + g11.y * a1.x;
            st[j0] = n0; st[j1] = n1;
        }
        // CNOT chain (c=0..6 adjacent) == index map: new[j] = old[j ^ (j>>1)]
        __syncthreads();
        int ja = t, jb = t + 128;
        float2 ra = st[ja ^ (ja >> 1)];
        float2 rb = st[jb ^ (jb >> 1)];
        __syncthreads();
        st[ja] = ra;
        st[jb] = rb;
    }
    __syncthreads();
    g_M[col][t] = st[t];
    g_M[col][t + 128] = st[t + 128];
}

// ---------------------------------------------------------------------------
// K2: one block per output wire i. Stage M in shared, compute the full real
// symmetric form B~_i[k,l] (256 threads = 256 (k,l)), then fold it into the
// separable 81-coefficient tensor C_i[m] via shared atomics.
// Sign of wire i handled by enumerating j with bit_i inserted (no per-j branch).
// ---------------------------------------------------------------------------
__global__ void setup_BC() {
    __shared__ float2 Ms[NCOL][DIM];     // 32 KB
    __shared__ float Csh[81];
    int t = threadIdx.x;                 // 0..255
    int i = blockIdx.x;                  // 0..7

    {
        const float2* src = &g_M[0][0];
        float2* dst = &Ms[0][0];
        for (int idx = t; idx < NCOL * DIM; idx += 256) dst[idx] = src[idx];
    }
    if (t < 81) Csh[t] = 0.f;
    __syncthreads();

    int k = t >> 4, l = t & 15;
    const float2* Mk = Ms[k];
    const float2* Ml = Ms[l];
    int bit = 1 << (7 - i);
    int mask = bit - 1;
    float ar = 0.f, ai = 0.f;
#pragma unroll 8
    for (int h = 0; h < 128; ++h) {
        int j0 = ((h & ~mask) << 1) | (h & mask);  // bit_i = 0  (+)
        int j1 = j0 | bit;                         // bit_i = 1  (-)
        float2 mk0 = Mk[j0], ml0 = Ml[j0];
        float2 mk1 = Mk[j1], ml1 = Ml[j1];
        ar += (mk0.x * ml0.x + mk0.y * ml0.y) - (mk1.x * ml1.x + mk1.y * ml1.y);
        ai += (mk0.x * ml0.y - mk0.y * ml0.x) - (mk1.x * ml1.y - mk1.y * ml1.x);
    }
    // multiply by encoding phase i^(popc(k)-popc(l)), take real part
    int d = (__popc(k) - __popc(l)) & 3;
    float val = (d == 0) ? ar : (d == 1) ? -ai : (d == 2) ? -ar : ai;

    // per-wire pair pattern digit: m_w = k_w + l_w  (0,1,2); (0,1)&(1,0) merge
    int m0 = ((k >> 3) & 1) + ((l >> 3) & 1);
    int m1 = ((k >> 2) & 1) + ((l >> 2) & 1);
    int m2 = ((k >> 1) & 1) + ((l >> 1) & 1);
    int m3 = (k & 1) + (l & 1);
    int m = m0 * 27 + m1 * 9 + m2 * 3 + m3;
    atomicAdd(&Csh[m], val);
    __syncthreads();
    if (t < 81) g_C[t * 8 + i] = Csh[t];
}

// ---------------------------------------------------------------------------
// K3: 1 thread per sample. u_w = (c^2, c*s, s^2) per feature wire;
// out_i = sum over 81 separable terms C_i[m] * u01[a] * u23[b].
// ---------------------------------------------------------------------------
__global__ void __launch_bounds__(256) qmain(const float* __restrict__ x,
                                             float* __restrict__ out) {
    __shared__ __align__(16) float Cs[81 * 8];
    int t = threadIdx.x;
    for (int idx = t; idx < 81 * 8; idx += 256) Cs[idx] = g_C[idx];
    __syncthreads();

    int b = blockIdx.x * 256 + t;
    float4 xv = reinterpret_cast<const float4*>(x)[b];

    const float QP = 0.78539816339744831f;  // pi/4
    float c0, s0, c1, s1, c2, s2, c3, s3;
    __sincosf((xv.x + 1.f) * QP, &s0, &c0);
    __sincosf((xv.y + 1.f) * QP, &s1, &c1);
    __sincosf((xv.z + 1.f) * QP, &s2, &c2);
    __sincosf((xv.w + 1.f) * QP, &s3, &c3);

    float u0[3] = {c0 * c0, c0 * s0, s0 * s0};
    float u1[3] = {c1 * c1, c1 * s1, s1 * s1};
    float u2[3] = {c2 * c2, c2 * s2, s2 * s2};
    float u3[3] = {c3 * c3, c3 * s3, s3 * s3};
    float u01[9], u23[9];
#pragma unroll
    for (int a = 0; a < 3; ++a)
#pragma unroll
        for (int c = 0; c < 3; ++c) {
            u01[a * 3 + c] = u0[a] * u1[c];
            u23[a * 3 + c] = u2[a] * u3[c];
        }

    float acc[8];
#pragma unroll
    for (int i = 0; i < 8; ++i) acc[i] = 0.f;
#pragma unroll
    for (int a = 0; a < 9; ++a) {
#pragma unroll
        for (int c = 0; c < 9; ++c) {
            float p = u01[a] * u23[c];
            const float4* cp = reinterpret_cast<const float4*>(&Cs[(a * 9 + c) * 8]);
            float4 b0 = cp[0], b1 = cp[1];
            acc[0] += b0.x * p; acc[1] += b0.y * p;
            acc[2] += b0.z * p; acc[3] += b0.w * p;
            acc[4] += b1.x * p; acc[5] += b1.y * p;
            acc[6] += b1.z * p; acc[7] += b1.w * p;
        }
    }

    float4* o = reinterpret_cast<float4*>(out + (size_t)b * 8);
    o[0] = make_float4(acc[0], acc[1], acc[2], acc[3]);
    o[1] = make_float4(acc[4], acc[5], acc[6], acc[7]);
}

// ---------------------------------------------------------------------------
extern "C" void kernel_launch(void* const* d_in, const int* in_sizes, int n_in,
                              void* d_out, int out_size) {
    const float* x = (const float*)d_in[0];        // (65536, 4)
    const float* params = (const float*)d_in[1];   // (2, 8, 3)
    float* out = (float*)d_out;                    // (65536, 8)

    setup_sim<<<16, 128>>>(params);
    setup_BC<<<8, 256>>>();
    qmain<<<BATCH / 256, 256>>>(x, out);
}

// round 3
// speedup vs baseline: 2.2128x; 2.2128x over previous
#include <cuda_runtime.h>

#define DIM 256
#define NCOL 16
#define BATCH 65536

// Scratch (no allocations allowed). M stored TRANSPOSED: g_Mt[j][col].
__device__ float2 g_Mt[DIM][NCOL];
__device__ float  g_C[81 * 8];      // separable quadratic-form tensor, [m][i]

__device__ __forceinline__ float2 cmul(float2 a, float2 b) {
    return make_float2(a.x * b.x - a.y * b.y, a.x * b.y + a.y * b.x);
}

// ---------------------------------------------------------------------------
// K1: simulate the variational circuit on the 16 relevant basis columns.
// One block per column; fused (RZ*RY*RX) 1q gates; CNOT chain collapsed to
// the closed-form permutation new[j] = old[j ^ (j>>1)].
// ---------------------------------------------------------------------------
__global__ void setup_sim(const float* __restrict__ params) {
    __shared__ float2 st[DIM];
    __shared__ float2 G[16][4];
    int t = threadIdx.x;            // 0..127
    int col = blockIdx.x;           // 0..15

    if (t < 16) {
        int layer = t >> 3, w = t & 7;
        const float* p = params + layer * 24 + w * 3;
        float cx, sx, cy, sy, cz, sz;
        sincosf(0.5f * p[0], &sx, &cx);
        sincosf(0.5f * p[1], &sy, &cy);
        sincosf(0.5f * p[2], &sz, &cz);
        float2 a00 = make_float2( cy * cx,  sy * sx);
        float2 a01 = make_float2(-sy * cx, -cy * sx);
        float2 a10 = make_float2( sy * cx, -cy * sx);
        float2 a11 = make_float2( cy * cx, -sy * sx);
        float2 e0 = make_float2(cz, -sz), e1 = make_float2(cz, sz);
        G[t][0] = cmul(e0, a00);
        G[t][1] = cmul(e0, a01);
        G[t][2] = cmul(e1, a10);
        G[t][3] = cmul(e1, a11);
    }
    st[t] = make_float2(0.f, 0.f);
    st[t + 128] = make_float2(0.f, 0.f);
    __syncthreads();
    if (t == 0) st[col << 4] = make_float2(1.f, 0.f);

    for (int layer = 0; layer < 2; ++layer) {
        for (int w = 0; w < 8; ++w) {
            __syncthreads();
            int bit = 1 << (7 - w);
            float2 g00 = G[layer * 8 + w][0], g01 = G[layer * 8 + w][1];
            float2 g10 = G[layer * 8 + w][2], g11 = G[layer * 8 + w][3];
            int j0 = ((t & ~(bit - 1)) << 1) | (t & (bit - 1));
            int j1 = j0 | bit;
            float2 a0 = st[j0], a1 = st[j1];
            float2 n0, n1;
            n0.x = g00.x * a0.x - g00.y * a0.y + g01.x * a1.x - g01.y * a1.y;
            n0.y = g00.x * a0.y + g00.y * a0.x + g01.x * a1.y + g01.y * a1.x;
            n1.x = g10.x * a0.x - g10.y * a0.y + g11.x * a1.x - g11.y * a1.y;
            n1.y = g10.x * a0.y + g10.y * a0.x + g11.x * a1.y + g11.y * a1.x;
            st[j0] = n0; st[j1] = n1;
        }
        __syncthreads();
        int ja = t, jb = t + 128;
        float2 ra = st[ja ^ (ja >> 1)];
        float2 rb = st[jb ^ (jb >> 1)];
        __syncthreads();
        st[ja] = ra;
        st[jb] = rb;
    }
    __syncthreads();
    g_Mt[t][col] = st[t];
    g_Mt[t + 128][col] = st[t + 128];
}

// ---------------------------------------------------------------------------
// K2: one block per output wire i. Stage Mt[j][k] in shared (128 B rows ->
// conflict-free: l-load contiguous, k-load broadcast). Thread t = (k,l) pair.
// Sign of wire i handled by bit-inserted index enumeration.
// ---------------------------------------------------------------------------
__global__ void setup_BC() {
    __shared__ float2 Ms[DIM][NCOL];     // 32 KB, row = 128 B
    __shared__ float Csh[81];
    int t = threadIdx.x;                 // 0..255
    int i = blockIdx.x;                  // 0..7

    {
        const float4* src = reinterpret_cast<const float4*>(&g_Mt[0][0]);
        float4* dst = reinterpret_cast<float4*>(&Ms[0][0]);
        for (int idx = t; idx < DIM * NCOL / 2; idx += 256) dst[idx] = src[idx];
    }
    if (t < 81) Csh[t] = 0.f;
    __syncthreads();

    int k = t >> 4, l = t & 15;
    int bit = 1 << (7 - i);
    int mask = bit - 1;
    float ar = 0.f, ai = 0.f;
#pragma unroll 8
    for (int h = 0; h < 128; ++h) {
        int j0 = ((h & ~mask) << 1) | (h & mask);  // bit_i = 0  (+)
        int j1 = j0 | bit;                         // bit_i = 1  (-)
        float2 mk0 = Ms[j0][k], ml0 = Ms[j0][l];
        float2 mk1 = Ms[j1][k], ml1 = Ms[j1][l];
        ar += (mk0.x * ml0.x + mk0.y * ml0.y) - (mk1.x * ml1.x + mk1.y * ml1.y);
        ai += (mk0.x * ml0.y - mk0.y * ml0.x) - (mk1.x * ml1.y - mk1.y * ml1.x);
    }
    int d = (__popc(k) - __popc(l)) & 3;
    float val = (d == 0) ? ar : (d == 1) ? -ai : (d == 2) ? -ar : ai;

    int m0 = ((k >> 3) & 1) + ((l >> 3) & 1);
    int m1 = ((k >> 2) & 1) + ((l >> 2) & 1);
    int m2 = ((k >> 1) & 1) + ((l >> 1) & 1);
    int m3 = (k & 1) + (l & 1);
    int m = m0 * 27 + m1 * 9 + m2 * 3 + m3;
    atomicAdd(&Csh[m], val);
    __syncthreads();
    if (t < 81) g_C[t * 8 + i] = Csh[t];
}

// ---------------------------------------------------------------------------
// K3: 4 samples per thread (strided by blockDim for coalescing); C staged in
// shared and each LDS.128 amortized over 4 samples. FFMA-bound by design.
// ---------------------------------------------------------------------------
__global__ void __launch_bounds__(128) qmain(const float* __restrict__ x,
                                             float* __restrict__ out) {
    __shared__ __align__(16) float Cs[81 * 8];
    int t = threadIdx.x;
    for (int idx = t; idx < 81 * 8; idx += 128) Cs[idx] = g_C[idx];
    __syncthreads();

    int s0 = blockIdx.x * 512 + t;   // samples s0 + 128*s, s=0..3
    const float QP = 0.78539816339744831f;  // pi/4

    float u01[4][9], u23[4][9];
#pragma unroll
    for (int s = 0; s < 4; ++s) {
        float4 xv = reinterpret_cast<const float4*>(x)[s0 + 128 * s];
        float c0, s_0, c1, s_1, c2, s_2, c3, s_3;
        __sincosf((xv.x + 1.f) * QP, &s_0, &c0);
        __sincosf((xv.y + 1.f) * QP, &s_1, &c1);
        __sincosf((xv.z + 1.f) * QP, &s_2, &c2);
        __sincosf((xv.w + 1.f) * QP, &s_3, &c3);
        float u0[3] = {c0 * c0, c0 * s_0, s_0 * s_0};
        float u1[3] = {c1 * c1, c1 * s_1, s_1 * s_1};
        float u2[3] = {c2 * c2, c2 * s_2, s_2 * s_2};
        float u3[3] = {c3 * c3, c3 * s_3, s_3 * s_3};
#pragma unroll
        for (int a = 0; a < 3; ++a)
#pragma unroll
            for (int c = 0; c < 3; ++c) {
                u01[s][a * 3 + c] = u0[a] * u1[c];
                u23[s][a * 3 + c] = u2[a] * u3[c];
            }
    }

    float acc[4][8];
#pragma unroll
    for (int s = 0; s < 4; ++s)
#pragma unroll
        for (int i = 0; i < 8; ++i) acc[s][i] = 0.f;

#pragma unroll
    for (int a = 0; a < 9; ++a) {
#pragma unroll
        for (int c = 0; c < 9; ++c) {
            const float4* cp = reinterpret_cast<const float4*>(&Cs[(a * 9 + c) * 8]);
            float4 b0 = cp[0], b1 = cp[1];
#pragma unroll
            for (int s = 0; s < 4; ++s) {
                float p = u01[s][a] * u23[s][c];
                acc[s][0] += b0.x * p; acc[s][1] += b0.y * p;
                acc[s][2] += b0.z * p; acc[s][3] += b0.w * p;
                acc[s][4] += b1.x * p; acc[s][5] += b1.y * p;
                acc[s][6] += b1.z * p; acc[s][7] += b1.w * p;
            }
        }
    }

#pragma unroll
    for (int s = 0; s < 4; ++s) {
        float4* o = reinterpret_cast<float4*>(out + (size_t)(s0 + 128 * s) * 8);
        o[0] = make_float4(acc[s][0], acc[s][1], acc[s][2], acc[s][3]);
        o[1] = make_float4(acc[s][4], acc[s][5], acc[s][6], acc[s][7]);
    }
}

// ---------------------------------------------------------------------------
extern "C" void kernel_launch(void* const* d_in, const int* in_sizes, int n_in,
                              void* d_out, int out_size) {
    const float* x = (const float*)d_in[0];        // (65536, 4)
    const float* params = (const float*)d_in[1];   // (2, 8, 3)
    float* out = (float*)d_out;                    // (65536, 8)

    setup_sim<<<16, 128>>>(params);
    setup_BC<<<8, 256>>>();
    qmain<<<BATCH / 512, 128>>>(x, out);
}

// round 4
// speedup vs baseline: 3.1618x; 1.4288x over previous
#include <cuda_runtime.h>

#define DIM 256
#define NCOL 16
#define BATCH 65536
typedef unsigned long long ull;

__device__ float2 g_Mt[DIM][NCOL];          // M transposed: [j][col]
__device__ float  g_C[81 * 8];              // separable tensor accumulator
__constant__ __align__(16) float c_C[81 * 8];

__device__ __forceinline__ float2 cmul(float2 a, float2 b) {
    return make_float2(a.x * b.x - a.y * b.y, a.x * b.y + a.y * b.x);
}
__device__ __forceinline__ void ffma2(ull& d, ull a, ull b) {
    asm("fma.rn.f32x2 %0, %1, %2, %0;" : "+l"(d) : "l"(a), "l"(b));
}
__device__ __forceinline__ ull dup2(float p) {
    ull r;
    asm("mov.b64 %0, {%1, %2};" : "=l"(r) : "f"(p), "f"(p));
    return r;
}

// ---------------------------------------------------------------------------
// K1: 16 blocks x 1 warp. Simulate the variational circuit on basis column
// |col>|0000>: fused RZ*RY*RX gates + CNOT chain as perm new[j]=old[j^(j>>1)].
// Warp-private smem state, __syncwarp only. Block 0 also zeroes g_C.
// ---------------------------------------------------------------------------
__global__ void setup_sim(const float* __restrict__ params) {
    __shared__ float2 st[DIM];
    __shared__ float2 Gs[16][4];
    int ln = threadIdx.x;            // 0..31
    int col = blockIdx.x;            // 0..15

    if (col == 0) {
        for (int idx = ln; idx < 81 * 8; idx += 32) g_C[idx] = 0.f;
    }

    if (ln < 16) {
        int layer = ln >> 3, w = ln & 7;
        const float* p = params + layer * 24 + w * 3;
        float cx, sx, cy, sy, cz, sz;
        __sincosf(0.5f * p[0], &sx, &cx);
        __sincosf(0.5f * p[1], &sy, &cy);
        __sincosf(0.5f * p[2], &sz, &cz);
        float2 a00 = make_float2( cy * cx,  sy * sx);
        float2 a01 = make_float2(-sy * cx, -cy * sx);
        float2 a10 = make_float2( sy * cx, -cy * sx);
        float2 a11 = make_float2( cy * cx, -sy * sx);
        float2 e0 = make_float2(cz, -sz), e1 = make_float2(cz, sz);
        Gs[ln][0] = cmul(e0, a00);
        Gs[ln][1] = cmul(e0, a01);
        Gs[ln][2] = cmul(e1, a10);
        Gs[ln][3] = cmul(e1, a11);
    }
#pragma unroll
    for (int r = 0; r < 8; ++r) st[ln + 32 * r] = make_float2(0.f, 0.f);
    __syncwarp();
    if (ln == 0) st[col << 4] = make_float2(1.f, 0.f);

    for (int layer = 0; layer < 2; ++layer) {
        for (int w = 0; w < 8; ++w) {
            __syncwarp();
            int g = layer * 8 + w;
            float2 g00 = Gs[g][0], g01 = Gs[g][1];
            float2 g10 = Gs[g][2], g11 = Gs[g][3];
            int bit = 1 << (7 - w);
#pragma unroll
            for (int r = 0; r < 4; ++r) {
                int h = ln + 32 * r;
                int j0 = ((h & ~(bit - 1)) << 1) | (h & (bit - 1));
                int j1 = j0 | bit;
                float2 a0 = st[j0], a1 = st[j1];
                float2 n0, n1;
                n0.x = g00.x * a0.x - g00.y * a0.y + g01.x * a1.x - g01.y * a1.y;
                n0.y = g00.x * a0.y + g00.y * a0.x + g01.x * a1.y + g01.y * a1.x;
                n1.x = g10.x * a0.x - g10.y * a0.y + g11.x * a1.x - g11.y * a1.y;
                n1.y = g10.x * a0.y + g10.y * a0.x + g11.x * a1.y + g11.y * a1.x;
                st[j0] = n0; st[j1] = n1;
            }
        }
        __syncwarp();
        float2 tmp[8];
#pragma unroll
        for (int r = 0; r < 8; ++r) {
            int j = ln + 32 * r;
            tmp[r] = st[j ^ (j >> 1)];
        }
        __syncwarp();
#pragma unroll
        for (int r = 0; r < 8; ++r) st[ln + 32 * r] = tmp[r];
    }
    __syncwarp();
#pragma unroll
    for (int r = 0; r < 8; ++r) {
        int j = ln + 32 * r;
        g_Mt[j][col] = st[j];
    }
}

// ---------------------------------------------------------------------------
// K2: 64 blocks = (8 wires) x (8 j-chunks of 32). Stage the chunk (4 KB),
// thread = (k,l) ordered pair, partial signed sums folded into the separable
// 81-class tensor; cross-block combine via atomics into g_C.
// ---------------------------------------------------------------------------
__global__ void setup_BC() {
    __shared__ float2 Ms[32][NCOL];      // 4 KB, row = 128 B (conflict-free)
    __shared__ float Csh[81];
    int t = threadIdx.x;                 // 0..255
    int i = blockIdx.x & 7;              // wire
    int q = blockIdx.x >> 3;             // j-chunk

    reinterpret_cast<float4*>(&Ms[0][0])[t] =
        reinterpret_cast<const float4*>(&g_Mt[q * 32][0])[t];
    if (t < 81) Csh[t] = 0.f;
    __syncthreads();

    int k = t >> 4, l = t & 15;
    int shift = 7 - i;
    float ar = 0.f, ai = 0.f;
#pragma unroll
    for (int jj = 0; jj < 32; ++jj) {
        int j = q * 32 + jj;
        float2 mk = Ms[jj][k], ml = Ms[jj][l];
        float pr = mk.x * ml.x + mk.y * ml.y;
        float pi = mk.x * ml.y - mk.y * ml.x;
        float sg = ((j >> shift) & 1) ? -1.f : 1.f;
        ar = fmaf(sg, pr, ar);
        ai = fmaf(sg, pi, ai);
    }
    int d = (__popc(k) - __popc(l)) & 3;
    float val = (d == 0) ? ar : (d == 1) ? -ai : (d == 2) ? -ar : ai;
    int m = (((k >> 3) & 1) + ((l >> 3) & 1)) * 27 +
            (((k >> 2) & 1) + ((l >> 2) & 1)) * 9 +
            (((k >> 1) & 1) + ((l >> 1) & 1)) * 3 +
            ((k & 1) + (l & 1));
    atomicAdd(&Csh[m], val);
    __syncthreads();
    if (t < 81) atomicAdd(&g_C[t * 8 + i], Csh[t]);
}

// ---------------------------------------------------------------------------
// K3: 2 samples/thread, f32x2 packed FFMA, C from __constant__ (const port,
// zero LDS in main loop). acc packed as output pairs (i, i+1) per sample.
// ---------------------------------------------------------------------------
__global__ void __launch_bounds__(256) qmain(const float* __restrict__ x,
                                             float* __restrict__ out) {
    int t = threadIdx.x;
    int s0 = blockIdx.x * 512 + t;       // second sample: s0 + 256
    const float QP = 0.78539816339744831f;  // pi/4

    float u01[2][9], u23[2][9];
#pragma unroll
    for (int s = 0; s < 2; ++s) {
        float4 xv = reinterpret_cast<const float4*>(x)[s0 + 256 * s];
        float c0, s_0, c1, s_1, c2, s_2, c3, s_3;
        __sincosf((xv.x + 1.f) * QP, &s_0, &c0);
        __sincosf((xv.y + 1.f) * QP, &s_1, &c1);
        __sincosf((xv.z + 1.f) * QP, &s_2, &c2);
        __sincosf((xv.w + 1.f) * QP, &s_3, &c3);
        float u0[3] = {c0 * c0, c0 * s_0, s_0 * s_0};
        float u1[3] = {c1 * c1, c1 * s_1, s_1 * s_1};
        float u2[3] = {c2 * c2, c2 * s_2, s_2 * s_2};
        float u3[3] = {c3 * c3, c3 * s_3, s_3 * s_3};
#pragma unroll
        for (int a = 0; a < 3; ++a)
#pragma unroll
            for (int c = 0; c < 3; ++c) {
                u01[s][a * 3 + c] = u0[a] * u1[c];
                u23[s][a * 3 + c] = u2[a] * u3[c];
            }
    }

    ull acc[2][4];
#pragma unroll
    for (int s = 0; s < 2; ++s)
#pragma unroll
        for (int p = 0; p < 4; ++p) acc[s][p] = 0ull;

#pragma unroll
    for (int a = 0; a < 9; ++a) {
#pragma unroll
        for (int c = 0; c < 9; ++c) {
            const ull* cp = reinterpret_cast<const ull*>(&c_C[(a * 9 + c) * 8]);
            ull c0 = cp[0], c1 = cp[1], c2 = cp[2], c3 = cp[3];
#pragma unroll
            for (int s = 0; s < 2; ++s) {
                ull pp = dup2(u01[s][a] * u23[s][c]);
                ffma2(acc[s][0], c0, pp);
                ffma2(acc[s][1], c1, pp);
                ffma2(acc[s][2], c2, pp);
                ffma2(acc[s][3], c3, pp);
            }
        }
    }

#pragma unroll
    for (int s = 0; s < 2; ++s) {
        float4* o = reinterpret_cast<float4*>(out + (size_t)(s0 + 256 * s) * 8);
        float2 p0 = *reinterpret_cast<float2*>(&acc[s][0]);
        float2 p1 = *reinterpret_cast<float2*>(&acc[s][1]);
        float2 p2 = *reinterpret_cast<float2*>(&acc[s][2]);
        float2 p3 = *reinterpret_cast<float2*>(&acc[s][3]);
        o[0] = make_float4(p0.x, p0.y, p1.x, p1.y);
        o[1] = make_float4(p2.x, p2.y, p3.x, p3.y);
    }
}

// ---------------------------------------------------------------------------
extern "C" void kernel_launch(void* const* d_in, const int* in_sizes, int n_in,
                              void* d_out, int out_size) {
    const float* x = (const float*)d_in[0];        // (65536, 4)
    const float* params = (const float*)d_in[1];   // (2, 8, 3)
    float* out = (float*)d_out;                    // (65536, 8)

    setup_sim<<<16, 32>>>(params);
    setup_BC<<<64, 256>>>();

    void* gc = nullptr;
    cudaGetSymbolAddress(&gc, g_C);
    cudaMemcpyToSymbolAsync(c_C, gc, 81 * 8 * sizeof(float), 0,
                            cudaMemcpyDeviceToDevice, 0);

    qmain<<<BATCH / 512, 256>>>(x, out);
}

// round 5
// speedup vs baseline: 3.1680x; 1.0020x over previous
#include <cuda_runtime.h>

#define DIM 256
#define NCOL 16
#define BATCH 65536
typedef unsigned long long ull;

__device__ float g_Cpart[8][81 * 8];   // per-j-chunk partial C tensors

__device__ __forceinline__ float2 cmul(float2 a, float2 b) {
    return make_float2(a.x * b.x - a.y * b.y, a.x * b.y + a.y * b.x);
}
__device__ __forceinline__ void ffma2(ull& d, ull a, ull b) {
    asm("fma.rn.f32x2 %0, %1, %2, %0;" : "+l"(d) : "l"(a), "l"(b));
}
__device__ __forceinline__ ull dup2(float p) {
    ull r;
    asm("mov.b64 %0, {%1, %2};" : "=l"(r) : "f"(p), "f"(p));
    return r;
}
__device__ __forceinline__ float2 shfl2(float2 v, int src) {
    float2 r;
    r.x = __shfl_sync(0xffffffffu, v.x, src);
    r.y = __shfl_sync(0xffffffffu, v.y, src);
    return r;
}

// swizzled smem index for M: row j (128 B), column XOR'd by j&15 -> conflict-free
#define SIDX(j, c) (((j) << 4) | ((c) ^ ((j) & 15)))

// ---------------------------------------------------------------------------
// K1 (fused): 64 blocks = (8 wires i) x (8 j-chunks q).
// Phase A: all-register sim of the 16 relevant columns (8 warps x 2 cols).
//   j bits: [0:5)=lane, [5:8)=reg. Wires 0-2 = reg-bit gates, 3-7 = shfl
//   gates, CNOT chain = closed-form shfl permutation new[j]=old[j^(j>>1)].
// Phase B: write M to swizzled smem; BC slice for (i, q) -> g_Cpart.
// ---------------------------------------------------------------------------
__global__ void __launch_bounds__(256) fused_setup(const float* __restrict__ params) {
    __shared__ float2 Ms[DIM * NCOL];    // 32 KB, swizzled
    __shared__ float2 G[16][4];
    __shared__ float Csh[81];

    int t = threadIdx.x;
    int ln = t & 31;
    int w = t >> 5;                      // warp id = column pair
    int i = blockIdx.x & 7;              // output wire
    int q = blockIdx.x >> 3;             // j chunk

    // fused per-(layer,wire) gates: G = RZ*RY*RX
    if (t < 16) {
        int layer = t >> 3, wi = t & 7;
        const float* p = params + layer * 24 + wi * 3;
        float cx, sx, cy, sy, cz, sz;
        __sincosf(0.5f * p[0], &sx, &cx);
        __sincosf(0.5f * p[1], &sy, &cy);
        __sincosf(0.5f * p[2], &sz, &cz);
        float2 a00 = make_float2( cy * cx,  sy * sx);
        float2 a01 = make_float2(-sy * cx, -cy * sx);
        float2 a10 = make_float2( sy * cx, -cy * sx);
        float2 a11 = make_float2( cy * cx, -sy * sx);
        float2 e0 = make_float2(cz, -sz), e1 = make_float2(cz, sz);
        G[t][0] = cmul(e0, a00);
        G[t][1] = cmul(e0, a01);
        G[t][2] = cmul(e1, a10);
        G[t][3] = cmul(e1, a11);
    }
    if (t < 81) Csh[t] = 0.f;
    __syncthreads();

    // -------- Phase A: register sim --------
    // st[h][r]: column c = 2w+h, amplitude j = ln + 32r
    float2 st[2][8];
#pragma unroll
    for (int h = 0; h < 2; ++h)
#pragma unroll
        for (int r = 0; r < 8; ++r)
            st[h][r] = make_float2((r == w && ln == (h << 4)) ? 1.f : 0.f, 0.f);

#pragma unroll
    for (int layer = 0; layer < 2; ++layer) {
#pragma unroll
        for (int wi = 0; wi < 8; ++wi) {
            int g = layer * 8 + wi;
            float2 g00 = G[g][0], g01 = G[g][1], g10 = G[g][2], g11 = G[g][3];
            if (wi < 3) {
                int rb = 1 << (2 - wi);   // reg-bit
#pragma unroll
                for (int h = 0; h < 2; ++h)
#pragma unroll
                    for (int r = 0; r < 8; ++r) {
                        if (r & rb) continue;
                        int r1 = r | rb;
                        float2 a0 = st[h][r], a1 = st[h][r1];
                        float2 n0, n1;
                        n0.x = g00.x * a0.x - g00.y * a0.y + g01.x * a1.x - g01.y * a1.y;
                        n0.y = g00.x * a0.y + g00.y * a0.x + g01.x * a1.y + g01.y * a1.x;
                        n1.x = g10.x * a0.x - g10.y * a0.y + g11.x * a1.x - g11.y * a1.y;
                        n1.y = g10.x * a0.y + g10.y * a0.x + g11.x * a1.y + g11.y * a1.x;
                        st[h][r] = n0; st[h][r1] = n1;
                    }
            } else {
                int mk = 1 << (7 - wi);   // lane-bit
                bool hi = (ln & mk) != 0;
                float2 ga = hi ? g11 : g00;   // coeff on my amp
                float2 gb = hi ? g10 : g01;   // coeff on partner amp
#pragma unroll
                for (int h = 0; h < 2; ++h)
#pragma unroll
                    for (int r = 0; r < 8; ++r) {
                        float2 m = st[h][r];
                        float2 p;
                        p.x = __shfl_xor_sync(0xffffffffu, m.x, mk);
                        p.y = __shfl_xor_sync(0xffffffffu, m.y, mk);
                        float2 n;
                        n.x = ga.x * m.x - ga.y * m.y + gb.x * p.x - gb.y * p.y;
                        n.y = ga.x * m.y + ga.y * m.x + gb.x * p.y + gb.y * p.x;
                        st[h][r] = n;
                    }
            }
        }
        // CNOT chain: new[j] = old[j ^ (j>>1)]
        int baseLane = (ln ^ (ln >> 1)) & 31;
        float2 tmp[2][8];
#pragma unroll
        for (int h = 0; h < 2; ++h)
#pragma unroll
            for (int r = 0; r < 8; ++r) {
                int sr = r ^ (r >> 1);
                int srcLane = baseLane ^ ((r & 1) << 4);
                tmp[h][r] = shfl2(st[h][sr], srcLane);
            }
#pragma unroll
        for (int h = 0; h < 2; ++h)
#pragma unroll
            for (int r = 0; r < 8; ++r) st[h][r] = tmp[h][r];
    }

    // write M to swizzled smem
#pragma unroll
    for (int h = 0; h < 2; ++h)
#pragma unroll
        for (int r = 0; r < 8; ++r) {
            int j = ln + 32 * r;
            Ms[SIDX(j, 2 * w + h)] = st[h][r];
        }
    __syncthreads();

    // -------- Phase B: BC slice (wire i, j in [32q, 32q+32)) --------
    int k = t >> 4, l = t & 15;
    int shift = 7 - i;
    float ar = 0.f, ai = 0.f;
#pragma unroll
    for (int jj = 0; jj < 32; ++jj) {
        int j = q * 32 + jj;
        float2 mk2 = Ms[SIDX(j, k)];
        float2 ml2 = Ms[SIDX(j, l)];
        float pr = mk2.x * ml2.x + mk2.y * ml2.y;
        float pi = mk2.x * ml2.y - mk2.y * ml2.x;
        float sg = ((j >> shift) & 1) ? -1.f : 1.f;
        ar = fmaf(sg, pr, ar);
        ai = fmaf(sg, pi, ai);
    }
    int d = (__popc(k) - __popc(l)) & 3;
    float val = (d == 0) ? ar : (d == 1) ? -ai : (d == 2) ? -ar : ai;
    int m = (((k >> 3) & 1) + ((l >> 3) & 1)) * 27 +
            (((k >> 2) & 1) + ((l >> 2) & 1)) * 9 +
            (((k >> 1) & 1) + ((l >> 1) & 1)) * 3 +
            ((k & 1) + (l & 1));
    atomicAdd(&Csh[m], val);
    __syncthreads();
    if (t < 81) g_Cpart[q][t * 8 + i] = Csh[t];
}

// ---------------------------------------------------------------------------
// K2: 2 samples/thread, f32x2 packed FFMA. C staged into smem by summing the
// 8 chunk-partials (L2-hit loads), inner loop reads via LDS.64.
// ---------------------------------------------------------------------------
__global__ void __launch_bounds__(256) qmain(const float* __restrict__ x,
                                             float* __restrict__ out) {
    __shared__ __align__(16) float Cs[81 * 8];
    int t = threadIdx.x;
    for (int idx = t; idx < 81 * 8; idx += 256) {
        float s = 0.f;
#pragma unroll
        for (int q = 0; q < 8; ++q) s += g_Cpart[q][idx];
        Cs[idx] = s;
    }
    __syncthreads();

    int s0 = blockIdx.x * 512 + t;       // second sample: s0 + 256
    const float QP = 0.78539816339744831f;  // pi/4

    float u01[2][9], u23[2][9];
#pragma unroll
    for (int s = 0; s < 2; ++s) {
        float4 xv = reinterpret_cast<const float4*>(x)[s0 + 256 * s];
        float c0, s_0, c1, s_1, c2, s_2, c3, s_3;
        __sincosf((xv.x + 1.f) * QP, &s_0, &c0);
        __sincosf((xv.y + 1.f) * QP, &s_1, &c1);
        __sincosf((xv.z + 1.f) * QP, &s_2, &c2);
        __sincosf((xv.w + 1.f) * QP, &s_3, &c3);
        float u0[3] = {c0 * c0, c0 * s_0, s_0 * s_0};
        float u1[3] = {c1 * c1, c1 * s_1, s_1 * s_1};
        float u2[3] = {c2 * c2, c2 * s_2, s_2 * s_2};
        float u3[3] = {c3 * c3, c3 * s_3, s_3 * s_3};
#pragma unroll
        for (int a = 0; a < 3; ++a)
#pragma unroll
            for (int c = 0; c < 3; ++c) {
                u01[s][a * 3 + c] = u0[a] * u1[c];
                u23[s][a * 3 + c] = u2[a] * u3[c];
            }
    }

    ull acc[2][4];
#pragma unroll
    for (int s = 0; s < 2; ++s)
#pragma unroll
        for (int p = 0; p < 4; ++p) acc[s][p] = 0ull;

#pragma unroll
    for (int a = 0; a < 9; ++a) {
#pragma unroll
        for (int c = 0; c < 9; ++c) {
            const ull* cp = reinterpret_cast<const ull*>(&Cs[(a * 9 + c) * 8]);
            ull c0 = cp[0], c1 = cp[1], c2 = cp[2], c3 = cp[3];
#pragma unroll
            for (int s = 0; s < 2; ++s) {
                ull pp = dup2(u01[s][a] * u23[s][c]);
                ffma2(acc[s][0], c0, pp);
                ffma2(acc[s][1], c1, pp);
                ffma2(acc[s][2], c2, pp);
                ffma2(acc[s][3], c3, pp);
            }
        }
    }

#pragma unroll
    for (int s = 0; s < 2; ++s) {
        float4* o = reinterpret_cast<float4*>(out + (size_t)(s0 + 256 * s) * 8);
        float2 p0 = *reinterpret_cast<float2*>(&acc[s][0]);
        float2 p1 = *reinterpret_cast<float2*>(&acc[s][1]);
        float2 p2 = *reinterpret_cast<float2*>(&acc[s][2]);
        float2 p3 = *reinterpret_cast<float2*>(&acc[s][3]);
        o[0] = make_float4(p0.x, p0.y, p1.x, p1.y);
        o[1] = make_float4(p2.x, p2.y, p3.x, p3.y);
    }
}

// ---------------------------------------------------------------------------
extern "C" void kernel_launch(void* const* d_in, const int* in_sizes, int n_in,
                              void* d_out, int out_size) {
    const float* x = (const float*)d_in[0];        // (65536, 4)
    const float* params = (const float*)d_in[1];   // (2, 8, 3)
    float* out = (float*)d_out;                    // (65536, 8)

    fused_setup<<<64, 256>>>(params);
    qmain<<<BATCH / 512, 256>>>(x, out);
}